// round 8
// baseline (speedup 1.0000x reference)
#include <cuda_runtime.h>
#include <cuda_fp16.h>

#define S_LEN 128
#define NH 8
#define INF9 1.0e9f

// Weight fragments in fp16 B-frag layout (uint = half2), prepped per launch.
__device__ unsigned g_Wfu[3 * 8 * 1024];   // [z][h][kg4][nf4][lane32][p2]
__device__ unsigned g_Wofu[8 * 1024];      // [h][kg2][nf8][lane32][p2]
// X in fp16 A-frag layout: [rtAbs 2048][kg4][lane32][reg4]
__device__ unsigned g_Xqf[2048 * 512];
__device__ unsigned g_Xkf[2048 * 512];

__device__ __forceinline__ unsigned pk(float a, float b) {
  __half2 h = __floats2half2_rn(a, b);
  return *(unsigned*)&h;
}

__device__ __forceinline__ void mma16(float4& c, unsigned a0, unsigned a1,
                                      unsigned a2, unsigned a3, unsigned b0,
                                      unsigned b1) {
  asm volatile(
      "mma.sync.aligned.m16n8k16.row.col.f32.f16.f16.f32 "
      "{%0,%1,%2,%3}, {%4,%5,%6,%7}, {%8,%9}, {%0,%1,%2,%3};"
      : "+f"(c.x), "+f"(c.y), "+f"(c.z), "+f"(c.w)
      : "r"(a0), "r"(a1), "r"(a2), "r"(a3), "r"(b0), "r"(b1));
}

// ---------------------------------------------------------------------------
// Prep: weights -> per-head fp16 B-frag layouts (wq pre-scaled by 1/sqrt(32)).
// ---------------------------------------------------------------------------
__global__ void prep_kernel(const float* __restrict__ wq,
                            const float* __restrict__ wk,
                            const float* __restrict__ wv,
                            const float* __restrict__ wo) {
  const float scale = 0.17677669529663687f;
  for (int id = blockIdx.x * 256 + threadIdx.x; id < 32768; id += 64 * 256) {
    if (id < 24576) {
      int p = id & 1, lane = (id >> 1) & 31, nf = (id >> 6) & 3,
          kg = (id >> 8) & 3, h = (id >> 10) & 7, z = id >> 13;
      int r4 = lane >> 2, c4 = lane & 3;
      const float* w = (z == 0) ? wq : (z == 1) ? wk : wv;
      int k0 = kg * 16 + 2 * c4 + 8 * p;
      int col = h * 32 + nf * 8 + r4;
      float v0 = w[k0 * 256 + col], v1 = w[(k0 + 1) * 256 + col];
      if (z == 0) { v0 *= scale; v1 *= scale; }
      g_Wfu[id] = pk(v0, v1);
    } else {
      int id2 = id - 24576;
      int p = id2 & 1, lane = (id2 >> 1) & 31, nf = (id2 >> 6) & 7,
          kg = (id2 >> 9) & 1, h = id2 >> 10;
      int r4 = lane >> 2, c4 = lane & 3;
      int k0 = kg * 16 + 2 * c4 + 8 * p;
      int col = nf * 8 + r4;
      g_Wofu[id2] = pk(wo[(h * 32 + k0) * 64 + col],
                       wo[(h * 32 + k0 + 1) * 64 + col]);
    }
  }
}

// ---------------------------------------------------------------------------
// Stage X (fp32 row-major) -> fp16 A-frag layout in global.
// A-frag: reg r (=eR+2*hi) at lane (r4*4+c4) = {X[row][k], X[row][k+1]}
// ---------------------------------------------------------------------------
__global__ void stagex_kernel(const float* __restrict__ xq,
                              const float* __restrict__ xkv) {
  int id = blockIdx.x * 256 + threadIdx.x;  // 524288 total
  int row = id >> 4, k0 = (id & 15) * 4;
  float4 a = *(const float4*)(xq + (size_t)row * 64 + k0);
  float4 b = *(const float4*)(xkv + (size_t)row * 64 + k0);
  int rt = row >> 4, kg = k0 >> 4;
  int rr = row & 15, r4s = rr & 7, eR = rr >> 3;
  int pi0 = (k0 & 15) >> 1;
  int c4a = pi0 & 3, hi = pi0 >> 2;
  int reg = eR + 2 * hi;
  int base = (((rt * 4 + kg) * 32 + r4s * 4 + c4a) * 4) + reg;
  g_Xqf[base] = pk(a.x, a.y);
  g_Xqf[base + 4] = pk(a.z, a.w);
  g_Xkf[base] = pk(b.x, b.y);
  g_Xkf[base + 4] = pk(b.z, b.w);
}

// ---------------------------------------------------------------------------
// Fused kernel: grid (s, qhalf) = 256 blocks x 256 threads, 2 blocks/SM.
// Warp owns 16 q rows (of this half's 128) and 32 kv rows (K/V proj).
// SMEM: Wsm[4096] Ks[4096] Vs[4096] ms[256 floats] = ~50 KB.
// ---------------------------------------------------------------------------
#define WS_OFF 0
#define KS_OFF 4096
#define VS_OFF 8192
#define MS_OFF 12288
#define FUSED_SMEM ((12288 + 256) * 4)

__global__ __launch_bounds__(256, 2) void fused_kernel(
    const float* __restrict__ mask, const float* __restrict__ bias,
    const float* __restrict__ bo, float* __restrict__ outg) {
  extern __shared__ unsigned smu[];
  float* ms = (float*)(smu + MS_OFF);

  const int tid = threadIdx.x;
  const int s = blockIdx.x, qh = blockIdx.y;

  ms[tid] = (mask[s * 256 + tid] - 1.0f) * INF9 - 4.0f;  // -4: exp headroom

  const int w = tid >> 5, lane = tid & 31;
  const int r4 = lane >> 2, c4 = lane & 3;

  const uint2* Ws2 = (const uint2*)(smu + WS_OFF);
  const uint2* Ks2 = (const uint2*)(smu + KS_OFF);
  const uint2* Vs2 = (const uint2*)(smu + VS_OFF);
  const uint4* Xqf4 = (const uint4*)g_Xqf;
  const uint4* Xkf4 = (const uint4*)g_Xkf;

  const int rtQ = s * 16 + qh * 8 + w;   // this warp's q row-tile (abs)
  const int ktB = s * 16 + w * 2;        // this warp's kv row-tiles (abs)

  float4 oacc[8];
#pragma unroll
  for (int j = 0; j < 8; j++) oacc[j] = make_float4(0.f, 0.f, 0.f, 0.f);

#pragma unroll 1
  for (int h = 0; h < NH; h++) {
    __syncthreads();  // prev head's Ks/Vs/Wsm reads done
    {
      uint4* dst = (uint4*)(smu + WS_OFF);
#pragma unroll
      for (int i = tid; i < 1024; i += 256) {
        int z = i >> 8, wi = i & 255;
        dst[i] = (z < 3) ? ((const uint4*)g_Wfu)[(z * 8 + h) * 256 + wi]
                         : ((const uint4*)g_Wofu)[h * 256 + wi];
      }
    }
    __syncthreads();

    // ---- Q = Xq @ Wq_h (16 rows) -> qa A-frags ----
    uint4 qa[2];
    {
      float4 acc[4];
#pragma unroll
      for (int j = 0; j < 4; j++) acc[j] = make_float4(0.f, 0.f, 0.f, 0.f);
#pragma unroll
      for (int kg = 0; kg < 4; kg++) {
        uint4 A = Xqf4[(rtQ * 4 + kg) * 32 + lane];
#pragma unroll
        for (int nf = 0; nf < 4; nf++) {
          uint2 B = Ws2[(kg * 4 + nf) * 32 + lane];
          mma16(acc[nf], A.x, A.y, A.z, A.w, B.x, B.y);
        }
      }
      qa[0] = make_uint4(pk(acc[0].x, acc[0].y), pk(acc[0].z, acc[0].w),
                         pk(acc[1].x, acc[1].y), pk(acc[1].z, acc[1].w));
      qa[1] = make_uint4(pk(acc[2].x, acc[2].y), pk(acc[2].z, acc[2].w),
                         pk(acc[3].x, acc[3].y), pk(acc[3].z, acc[3].w));
    }

    // ---- K = Xkv @ Wk_h (32 rows) -> Ks scatter ----
    {
      float4 acc[2][4];
#pragma unroll
      for (int i = 0; i < 2; i++)
#pragma unroll
        for (int j = 0; j < 4; j++) acc[i][j] = make_float4(0.f, 0.f, 0.f, 0.f);
#pragma unroll
      for (int kg = 0; kg < 4; kg++) {
        uint4 A0 = Xkf4[((ktB + 0) * 4 + kg) * 32 + lane];
        uint4 A1 = Xkf4[((ktB + 1) * 4 + kg) * 32 + lane];
#pragma unroll
        for (int nf = 0; nf < 4; nf++) {
          uint2 B = Ws2[512 + (kg * 4 + nf) * 32 + lane];
          mma16(acc[0][nf], A0.x, A0.y, A0.z, A0.w, B.x, B.y);
          mma16(acc[1][nf], A1.x, A1.y, A1.z, A1.w, B.x, B.y);
        }
      }
#pragma unroll
      for (int mt = 0; mt < 2; mt++) {
        int kt = w * 2 + mt;
#pragma unroll
        for (int nf = 0; nf < 4; nf++) {
          int kgd = nf >> 1, p = nf & 1;
          smu[KS_OFF + (((kt * 2 + kgd) * 2 + 0) * 32 + lane) * 2 + p] =
              pk(acc[mt][nf].x, acc[mt][nf].y);
          smu[KS_OFF + (((kt * 2 + kgd) * 2 + 1) * 32 + lane) * 2 + p] =
              pk(acc[mt][nf].z, acc[mt][nf].w);
        }
      }
    }

    // ---- V = Xkv @ Wv_h (32 rows) -> Vs scatter ----
    {
      float4 acc[2][4];
#pragma unroll
      for (int i = 0; i < 2; i++)
#pragma unroll
        for (int j = 0; j < 4; j++) acc[i][j] = make_float4(0.f, 0.f, 0.f, 0.f);
#pragma unroll
      for (int kg = 0; kg < 4; kg++) {
        uint4 A0 = Xkf4[((ktB + 0) * 4 + kg) * 32 + lane];
        uint4 A1 = Xkf4[((ktB + 1) * 4 + kg) * 32 + lane];
#pragma unroll
        for (int nf = 0; nf < 4; nf++) {
          uint2 B = Ws2[1024 + (kg * 4 + nf) * 32 + lane];
          mma16(acc[0][nf], A0.x, A0.y, A0.z, A0.w, B.x, B.y);
          mma16(acc[1][nf], A1.x, A1.y, A1.z, A1.w, B.x, B.y);
        }
      }
      __half* Vh = (__half*)(smu + VS_OFF);
      int e = r4 & 1, cp = r4 >> 1;
#pragma unroll
      for (int mt = 0; mt < 2; mt++) {
        int kt = w * 2 + mt;
#pragma unroll
        for (int nf = 0; nf < 4; nf++) {
          int b0 = (((kt * 4 + nf) * 32 + (2 * c4) * 4 + cp) * 4) + e;
          int b1 = b0 + 16;
          Vh[b0] = __float2half_rn(acc[mt][nf].x);
          Vh[b0 + 2] = __float2half_rn(acc[mt][nf].z);
          Vh[b1] = __float2half_rn(acc[mt][nf].y);
          Vh[b1 + 2] = __float2half_rn(acc[mt][nf].w);
        }
      }
    }
    __syncthreads();  // Ks/Vs ready

    // ---- attention (16 q rows per warp) ----
    float4 o[4];
#pragma unroll
    for (int nf = 0; nf < 4; nf++) o[nf] = make_float4(0.f, 0.f, 0.f, 0.f);
    float2 lp = make_float2(0.f, 0.f);

    const float* Bh = bias + (size_t)h * 65536;
    const float* bb0 = Bh + (size_t)(qh * 128 + w * 16 + r4) * 256 + 2 * c4;
    const float* bb1 = bb0 + 8 * 256;
    float2 cb[2][2];  // [nt][rowpair]
#pragma unroll
    for (int nt = 0; nt < 2; nt++) {
      cb[nt][0] = *(const float2*)(bb0 + nt * 8);
      cb[nt][1] = *(const float2*)(bb1 + nt * 8);
    }

#pragma unroll 1
    for (int kt = 0; kt < 16; kt++) {
      const int kv0 = kt * 16;

      float2 nb[2][2];
      if (kt < 15) {
#pragma unroll
        for (int nt = 0; nt < 2; nt++) {
          nb[nt][0] = *(const float2*)(bb0 + kv0 + 16 + nt * 8);
          nb[nt][1] = *(const float2*)(bb1 + kv0 + 16 + nt * 8);
        }
      }

      float2 m0 = *(const float2*)(ms + kv0 + 2 * c4);
      float2 m1 = *(const float2*)(ms + kv0 + 8 + 2 * c4);

      float4 Sf[2];
      Sf[0] = make_float4(cb[0][0].x + m0.x, cb[0][0].y + m0.y,
                          cb[0][1].x + m0.x, cb[0][1].y + m0.y);
      Sf[1] = make_float4(cb[1][0].x + m1.x, cb[1][0].y + m1.y,
                          cb[1][1].x + m1.x, cb[1][1].y + m1.y);

#pragma unroll
      for (int kg = 0; kg < 2; kg++) {
        uint2 Kb0 = Ks2[((kt * 2 + kg) * 2 + 0) * 32 + lane];
        uint2 Kb1 = Ks2[((kt * 2 + kg) * 2 + 1) * 32 + lane];
        mma16(Sf[0], qa[kg].x, qa[kg].y, qa[kg].z, qa[kg].w, Kb0.x, Kb0.y);
        mma16(Sf[1], qa[kg].x, qa[kg].y, qa[kg].z, qa[kg].w, Kb1.x, Kb1.y);
      }

      uint2 Vb[4];
#pragma unroll
      for (int nf = 0; nf < 4; nf++) Vb[nf] = Vs2[(kt * 4 + nf) * 32 + lane];

      float p00 = __expf(Sf[0].x), p01 = __expf(Sf[0].y);
      float p02 = __expf(Sf[0].z), p03 = __expf(Sf[0].w);
      float p10 = __expf(Sf[1].x), p11 = __expf(Sf[1].y);
      float p12 = __expf(Sf[1].z), p13 = __expf(Sf[1].w);
      lp.x += (p00 + p01) + (p10 + p11);
      lp.y += (p02 + p03) + (p12 + p13);
      unsigned pa0 = pk(p00, p01), pa1 = pk(p02, p03);
      unsigned pa2 = pk(p10, p11), pa3 = pk(p12, p13);
#pragma unroll
      for (int nf = 0; nf < 4; nf++)
        mma16(o[nf], pa0, pa1, pa2, pa3, Vb[nf].x, Vb[nf].y);

      if (kt < 15) {
#pragma unroll
        for (int nt = 0; nt < 2; nt++) { cb[nt][0] = nb[nt][0]; cb[nt][1] = nb[nt][1]; }
      }
    }

    // ---- normalize O, pack to A-frags, oacc += O @ Wo_h ----
    lp.x += __shfl_xor_sync(0xffffffffu, lp.x, 1);
    lp.x += __shfl_xor_sync(0xffffffffu, lp.x, 2);
    lp.y += __shfl_xor_sync(0xffffffffu, lp.y, 1);
    lp.y += __shfl_xor_sync(0xffffffffu, lp.y, 2);
    float inv0 = 1.0f / lp.x;
    float inv8 = 1.0f / lp.y;
#pragma unroll
    for (int kg = 0; kg < 2; kg++) {
      unsigned oa0 = pk(o[2 * kg].x * inv0, o[2 * kg].y * inv0);
      unsigned oa1 = pk(o[2 * kg].z * inv8, o[2 * kg].w * inv8);
      unsigned oa2 = pk(o[2 * kg + 1].x * inv0, o[2 * kg + 1].y * inv0);
      unsigned oa3 = pk(o[2 * kg + 1].z * inv8, o[2 * kg + 1].w * inv8);
#pragma unroll
      for (int nf = 0; nf < 8; nf++) {
        uint2 B = Ws2[1536 + (kg * 8 + nf) * 32 + lane];
        mma16(oacc[nf], oa0, oa1, oa2, oa3, B.x, B.y);
      }
    }
  }

  // ---- epilogue: + bo, store ----
  {
    int row = s * 256 + qh * 128 + w * 16 + r4;
#pragma unroll
    for (int nf = 0; nf < 8; nf++) {
      int col = nf * 8 + 2 * c4;
      float2 bb = *(const float2*)(bo + col);
      *(float2*)(outg + (size_t)row * 64 + col) =
          make_float2(oacc[nf].x + bb.x, oacc[nf].y + bb.y);
      *(float2*)(outg + (size_t)(row + 8) * 64 + col) =
          make_float2(oacc[nf].z + bb.x, oacc[nf].w + bb.y);
    }
  }
}

// ---------------------------------------------------------------------------
extern "C" void kernel_launch(void* const* d_in, const int* in_sizes, int n_in,
                              void* d_out, int out_size) {
  const float* input_q  = (const float*)d_in[0];
  const float* input_kv = (const float*)d_in[1];
  const float* mask     = (const float*)d_in[2];
  const float* bias     = (const float*)d_in[3];
  const float* wq       = (const float*)d_in[4];
  const float* wk       = (const float*)d_in[5];
  const float* wv       = (const float*)d_in[6];
  const float* wo       = (const float*)d_in[7];
  const float* bo       = (const float*)d_in[8];
  float* out = (float*)d_out;

  cudaFuncSetAttribute(fused_kernel, cudaFuncAttributeMaxDynamicSharedMemorySize,
                       FUSED_SMEM);

  prep_kernel<<<64, 256>>>(wq, wk, wv, wo);
  stagex_kernel<<<2048, 256>>>(input_q, input_kv);
  fused_kernel<<<dim3(S_LEN, 2), 256, FUSED_SMEM>>>(mask, bias, bo, out);
}

// round 9
// speedup vs baseline: 1.2044x; 1.2044x over previous
#include <cuda_runtime.h>
#include <cuda_fp16.h>

#define S_LEN 128
#define NH 8
#define INF9 1.0e9f

// Weight fragments in fp16 B-frag layout (uint = half2), prepped per launch.
__device__ unsigned g_Wfu[3 * 8 * 1024];   // [z][h][kg4][nf4][lane32][p2]
__device__ unsigned g_Wofu[8 * 1024];      // [h][kg2][nf8][lane32][p2]
__device__ unsigned g_B16[1048576];        // bias as half2 pairs (same order)

__device__ __forceinline__ unsigned pk(float a, float b) {
  __half2 h = __floats2half2_rn(a, b);
  return *(unsigned*)&h;
}
__device__ __forceinline__ float2 h22f2(unsigned u) {
  __half2 h = *(__half2*)&u;
  return __half22float2(h);
}

// D += A(16x16 f16) * B(16x8 f16), fp32 accum.
__device__ __forceinline__ void mma16(float4& c, unsigned a0, unsigned a1,
                                      unsigned a2, unsigned a3, unsigned b0,
                                      unsigned b1) {
  asm volatile(
      "mma.sync.aligned.m16n8k16.row.col.f32.f16.f16.f32 "
      "{%0,%1,%2,%3}, {%4,%5,%6,%7}, {%8,%9}, {%0,%1,%2,%3};"
      : "+f"(c.x), "+f"(c.y), "+f"(c.z), "+f"(c.w)
      : "r"(a0), "r"(a1), "r"(a2), "r"(a3), "r"(b0), "r"(b1));
}

// ---------------------------------------------------------------------------
// Prep: weights -> per-head fp16 B-frag layouts (wq pre-scaled by 1/sqrt(32)).
// ---------------------------------------------------------------------------
__global__ void prep_kernel(const float* __restrict__ wq,
                            const float* __restrict__ wk,
                            const float* __restrict__ wv,
                            const float* __restrict__ wo) {
  const float scale = 0.17677669529663687f;
  int id = blockIdx.x * 256 + threadIdx.x;  // 32768 total
  if (id < 24576) {
    int p = id & 1, lane = (id >> 1) & 31, nf = (id >> 6) & 3,
        kg = (id >> 8) & 3, h = (id >> 10) & 7, z = id >> 13;
    int r4 = lane >> 2, c4 = lane & 3;
    const float* w = (z == 0) ? wq : (z == 1) ? wk : wv;
    int k0 = kg * 16 + 2 * c4 + 8 * p;
    int col = h * 32 + nf * 8 + r4;
    float v0 = w[k0 * 256 + col], v1 = w[(k0 + 1) * 256 + col];
    if (z == 0) { v0 *= scale; v1 *= scale; }
    g_Wfu[id] = pk(v0, v1);
  } else {
    int id2 = id - 24576;
    int p = id2 & 1, lane = (id2 >> 1) & 31, nf = (id2 >> 6) & 7,
        kg = (id2 >> 9) & 1, h = id2 >> 10;
    int r4 = lane >> 2, c4 = lane & 3;
    int k0 = kg * 16 + 2 * c4 + 8 * p;
    int col = nf * 8 + r4;
    g_Wofu[id2] = pk(wo[(h * 32 + k0) * 64 + col],
                     wo[(h * 32 + k0 + 1) * 64 + col]);
  }
}

// bias fp32 -> fp16 (pairs), identical element order.
__global__ void stageb_kernel(const float* __restrict__ bias) {
  int id = blockIdx.x * 256 + threadIdx.x;  // 1048576 total
  float2 v = ((const float2*)bias)[id];
  g_B16[id] = pk(v.x, v.y);
}

// ---------------------------------------------------------------------------
// Mega-fused kernel: one block per s, 256 threads (8 warps), warp owns 32
// rows (q and kv). fp16 operands, fp32 accum, double-buffered W/Ks/Vs
// (2 syncthreads per head), fp16 bias stream.
//
// SMEM (uints): Xq[8192] Xk[8192] W[2x4096] Ks[2x4096] Vs[2x4096] ms[256f]
// ---------------------------------------------------------------------------
#define XQ_OFF 0
#define XK_OFF 8192
#define WS_OFF 16384
#define KS_OFF 24576
#define VS_OFF 32768
#define MS_OFF 40960
#define FUSED_SMEM ((40960 + 256) * 4)

__global__ __launch_bounds__(256, 1) void fused_kernel(
    const float* __restrict__ xq, const float* __restrict__ xkv,
    const float* __restrict__ mask, const float* __restrict__ bo,
    float* __restrict__ outg) {
  extern __shared__ unsigned smu[];
  float* ms = (float*)(smu + MS_OFF);

  const int tid = threadIdx.x;
  const int s = blockIdx.x;

  // ---- stage Xq, Xkv as fp16 A-frags ----
  for (int i = tid; i < 4096; i += 256) {
    int row = i >> 4, k0 = (i & 15) * 4;
    float4 a = *(const float4*)(xq + (size_t)(s * 256 + row) * 64 + k0);
    float4 b = *(const float4*)(xkv + (size_t)(s * 256 + row) * 64 + k0);
    int rt = row >> 4, kg = k0 >> 4;
    int r4s = row & 7, eR = (row >> 3) & 1;
    int pi0 = (k0 & 15) >> 1;
    int c4a = pi0 & 3, hi = pi0 >> 2;
    int reg = eR + 2 * hi;
    int base = (((rt * 4 + kg) * 32 + r4s * 4 + c4a) * 4) + reg;
    smu[XQ_OFF + base] = pk(a.x, a.y);
    smu[XQ_OFF + base + 4] = pk(a.z, a.w);
    smu[XK_OFF + base] = pk(b.x, b.y);
    smu[XK_OFF + base + 4] = pk(b.z, b.w);
  }
  ms[tid] = (mask[s * 256 + tid] - 1.0f) * INF9 - 4.0f;  // -4: exp headroom

  const int w = tid >> 5, lane = tid & 31;
  const int r4 = lane >> 2, c4 = lane & 3;
  const int rt0 = w * 2;

  const uint4* Xq4 = (const uint4*)(smu + XQ_OFF);
  const uint4* Xk4 = (const uint4*)(smu + XK_OFF);

  float4 oacc[2][8];
#pragma unroll
  for (int i = 0; i < 2; i++)
#pragma unroll
    for (int j = 0; j < 8; j++) oacc[i][j] = make_float4(0.f, 0.f, 0.f, 0.f);

#pragma unroll 1
  for (int h = 0; h < NH; h++) {
    const int p = h & 1;
    const uint2* Ws2 = (const uint2*)(smu + WS_OFF + p * 4096);
    const uint2* Ks2 = (const uint2*)(smu + KS_OFF + p * 4096);
    const uint2* Vs2 = (const uint2*)(smu + VS_OFF + p * 4096);

    // stage W frags into parity buffer (safe: last written 2 heads ago)
    {
      uint4* dst = (uint4*)(smu + WS_OFF + p * 4096);
#pragma unroll
      for (int i = tid; i < 1024; i += 256) {
        int z = i >> 8, wi = i & 255;
        dst[i] = (z < 3) ? ((const uint4*)g_Wfu)[(z * 8 + h) * 256 + wi]
                         : ((const uint4*)g_Wofu)[h * 256 + wi];
      }
    }
    __syncthreads();  // W[p] visible (and X staging on h=0)

    // ---- Q = Xq @ Wq_h -> qa A-frags ----
    uint4 qa[2][2];
    {
      float4 acc[2][4];
#pragma unroll
      for (int i = 0; i < 2; i++)
#pragma unroll
        for (int j = 0; j < 4; j++) acc[i][j] = make_float4(0.f, 0.f, 0.f, 0.f);
#pragma unroll
      for (int kg = 0; kg < 4; kg++) {
        uint4 A0 = Xq4[(rt0 * 4 + kg) * 32 + lane];
        uint4 A1 = Xq4[((rt0 + 1) * 4 + kg) * 32 + lane];
#pragma unroll
        for (int nf = 0; nf < 4; nf++) {
          uint2 B = Ws2[(kg * 4 + nf) * 32 + lane];
          mma16(acc[0][nf], A0.x, A0.y, A0.z, A0.w, B.x, B.y);
          mma16(acc[1][nf], A1.x, A1.y, A1.z, A1.w, B.x, B.y);
        }
      }
#pragma unroll
      for (int mt = 0; mt < 2; mt++)
#pragma unroll
        for (int kg = 0; kg < 2; kg++)
          qa[mt][kg] = make_uint4(pk(acc[mt][2 * kg].x, acc[mt][2 * kg].y),
                                  pk(acc[mt][2 * kg].z, acc[mt][2 * kg].w),
                                  pk(acc[mt][2 * kg + 1].x, acc[mt][2 * kg + 1].y),
                                  pk(acc[mt][2 * kg + 1].z, acc[mt][2 * kg + 1].w));
    }

    // ---- K = Xkv @ Wk_h -> Ks[p] scatter ----
    {
      float4 acc[2][4];
#pragma unroll
      for (int i = 0; i < 2; i++)
#pragma unroll
        for (int j = 0; j < 4; j++) acc[i][j] = make_float4(0.f, 0.f, 0.f, 0.f);
#pragma unroll
      for (int kg = 0; kg < 4; kg++) {
        uint4 A0 = Xk4[(rt0 * 4 + kg) * 32 + lane];
        uint4 A1 = Xk4[((rt0 + 1) * 4 + kg) * 32 + lane];
#pragma unroll
        for (int nf = 0; nf < 4; nf++) {
          uint2 B = Ws2[512 + (kg * 4 + nf) * 32 + lane];
          mma16(acc[0][nf], A0.x, A0.y, A0.z, A0.w, B.x, B.y);
          mma16(acc[1][nf], A1.x, A1.y, A1.z, A1.w, B.x, B.y);
        }
      }
#pragma unroll
      for (int mt = 0; mt < 2; mt++) {
        int kt = w * 2 + mt;
#pragma unroll
        for (int nf = 0; nf < 4; nf++) {
          int kgd = nf >> 1, pp = nf & 1;
          smu[KS_OFF + p * 4096 + (((kt * 2 + kgd) * 2 + 0) * 32 + lane) * 2 + pp] =
              pk(acc[mt][nf].x, acc[mt][nf].y);
          smu[KS_OFF + p * 4096 + (((kt * 2 + kgd) * 2 + 1) * 32 + lane) * 2 + pp] =
              pk(acc[mt][nf].z, acc[mt][nf].w);
        }
      }
    }

    // ---- V = Xkv @ Wv_h -> Vs[p] scatter ----
    {
      float4 acc[2][4];
#pragma unroll
      for (int i = 0; i < 2; i++)
#pragma unroll
        for (int j = 0; j < 4; j++) acc[i][j] = make_float4(0.f, 0.f, 0.f, 0.f);
#pragma unroll
      for (int kg = 0; kg < 4; kg++) {
        uint4 A0 = Xk4[(rt0 * 4 + kg) * 32 + lane];
        uint4 A1 = Xk4[((rt0 + 1) * 4 + kg) * 32 + lane];
#pragma unroll
        for (int nf = 0; nf < 4; nf++) {
          uint2 B = Ws2[1024 + (kg * 4 + nf) * 32 + lane];
          mma16(acc[0][nf], A0.x, A0.y, A0.z, A0.w, B.x, B.y);
          mma16(acc[1][nf], A1.x, A1.y, A1.z, A1.w, B.x, B.y);
        }
      }
      __half* Vh = (__half*)(smu + VS_OFF + p * 4096);
      int e = r4 & 1, cp = r4 >> 1;
#pragma unroll
      for (int mt = 0; mt < 2; mt++) {
        int kt = w * 2 + mt;
#pragma unroll
        for (int nf = 0; nf < 4; nf++) {
          int b0 = (((kt * 4 + nf) * 32 + (2 * c4) * 4 + cp) * 4) + e;
          int b1 = b0 + 16;
          Vh[b0] = __float2half_rn(acc[mt][nf].x);
          Vh[b0 + 2] = __float2half_rn(acc[mt][nf].z);
          Vh[b1] = __float2half_rn(acc[mt][nf].y);
          Vh[b1 + 2] = __float2half_rn(acc[mt][nf].w);
        }
      }
    }
    __syncthreads();  // Ks/Vs[p] ready

    // ---- attention ----
    float4 o[2][4];
#pragma unroll
    for (int mt = 0; mt < 2; mt++)
#pragma unroll
      for (int nf = 0; nf < 4; nf++) o[mt][nf] = make_float4(0.f, 0.f, 0.f, 0.f);
    float2 lp[2] = {make_float2(0.f, 0.f), make_float2(0.f, 0.f)};

    const unsigned* bb0[2]; const unsigned* bb1[2];
#pragma unroll
    for (int mt = 0; mt < 2; mt++) {
      bb0[mt] = g_B16 + h * 32768 + (w * 32 + mt * 16 + r4) * 128 + c4;
      bb1[mt] = bb0[mt] + 8 * 128;
    }
    unsigned cb[2][2][2];  // [mt][nt][rowpair] half2 pairs
#pragma unroll
    for (int mt = 0; mt < 2; mt++)
#pragma unroll
      for (int nt = 0; nt < 2; nt++) {
        cb[mt][nt][0] = bb0[mt][nt * 4];
        cb[mt][nt][1] = bb1[mt][nt * 4];
      }

#pragma unroll 2
    for (int kt = 0; kt < 16; kt++) {
      const int kv0 = kt * 16;

      unsigned nb[2][2][2];
      if (kt < 15) {
#pragma unroll
        for (int mt = 0; mt < 2; mt++)
#pragma unroll
          for (int nt = 0; nt < 2; nt++) {
            nb[mt][nt][0] = bb0[mt][kt * 8 + 8 + nt * 4];
            nb[mt][nt][1] = bb1[mt][kt * 8 + 8 + nt * 4];
          }
      }

      float2 m0 = *(const float2*)(ms + kv0 + 2 * c4);
      float2 m1 = *(const float2*)(ms + kv0 + 8 + 2 * c4);

      float4 Sf[2][2];
#pragma unroll
      for (int mt = 0; mt < 2; mt++) {
        float2 c00 = h22f2(cb[mt][0][0]), c01 = h22f2(cb[mt][0][1]);
        float2 c10 = h22f2(cb[mt][1][0]), c11 = h22f2(cb[mt][1][1]);
        Sf[mt][0] = make_float4(c00.x + m0.x, c00.y + m0.y,
                                c01.x + m0.x, c01.y + m0.y);
        Sf[mt][1] = make_float4(c10.x + m1.x, c10.y + m1.y,
                                c11.x + m1.x, c11.y + m1.y);
      }

#pragma unroll
      for (int kg = 0; kg < 2; kg++) {
        uint2 Kb0 = Ks2[((kt * 2 + kg) * 2 + 0) * 32 + lane];
        uint2 Kb1 = Ks2[((kt * 2 + kg) * 2 + 1) * 32 + lane];
#pragma unroll
        for (int mt = 0; mt < 2; mt++) {
          mma16(Sf[mt][0], qa[mt][kg].x, qa[mt][kg].y, qa[mt][kg].z,
                qa[mt][kg].w, Kb0.x, Kb0.y);
          mma16(Sf[mt][1], qa[mt][kg].x, qa[mt][kg].y, qa[mt][kg].z,
                qa[mt][kg].w, Kb1.x, Kb1.y);
        }
      }

      uint2 Vb[4];
#pragma unroll
      for (int nf = 0; nf < 4; nf++) Vb[nf] = Vs2[(kt * 4 + nf) * 32 + lane];

#pragma unroll
      for (int mt = 0; mt < 2; mt++) {
        float p00 = __expf(Sf[mt][0].x), p01 = __expf(Sf[mt][0].y);
        float p02 = __expf(Sf[mt][0].z), p03 = __expf(Sf[mt][0].w);
        float p10 = __expf(Sf[mt][1].x), p11 = __expf(Sf[mt][1].y);
        float p12 = __expf(Sf[mt][1].z), p13 = __expf(Sf[mt][1].w);
        lp[mt].x += (p00 + p01) + (p10 + p11);
        lp[mt].y += (p02 + p03) + (p12 + p13);
        unsigned pa0 = pk(p00, p01), pa1 = pk(p02, p03);
        unsigned pa2 = pk(p10, p11), pa3 = pk(p12, p13);
#pragma unroll
        for (int nf = 0; nf < 4; nf++)
          mma16(o[mt][nf], pa0, pa1, pa2, pa3, Vb[nf].x, Vb[nf].y);
      }

      if (kt < 15) {
#pragma unroll
        for (int mt = 0; mt < 2; mt++)
#pragma unroll
          for (int nt = 0; nt < 2; nt++) {
            cb[mt][nt][0] = nb[mt][nt][0];
            cb[mt][nt][1] = nb[mt][nt][1];
          }
      }
    }

    // ---- normalize O, pack to A-frags, oacc += O @ Wo_h ----
#pragma unroll
    for (int mt = 0; mt < 2; mt++) {
      lp[mt].x += __shfl_xor_sync(0xffffffffu, lp[mt].x, 1);
      lp[mt].x += __shfl_xor_sync(0xffffffffu, lp[mt].x, 2);
      lp[mt].y += __shfl_xor_sync(0xffffffffu, lp[mt].y, 1);
      lp[mt].y += __shfl_xor_sync(0xffffffffu, lp[mt].y, 2);
      float inv0 = 1.0f / lp[mt].x;
      float inv8 = 1.0f / lp[mt].y;
#pragma unroll
      for (int kg = 0; kg < 2; kg++) {
        unsigned oa0 = pk(o[mt][2 * kg].x * inv0, o[mt][2 * kg].y * inv0);
        unsigned oa1 = pk(o[mt][2 * kg].z * inv8, o[mt][2 * kg].w * inv8);
        unsigned oa2 = pk(o[mt][2 * kg + 1].x * inv0, o[mt][2 * kg + 1].y * inv0);
        unsigned oa3 = pk(o[mt][2 * kg + 1].z * inv8, o[mt][2 * kg + 1].w * inv8);
#pragma unroll
        for (int nf = 0; nf < 8; nf++) {
          uint2 B = Ws2[1536 + (kg * 8 + nf) * 32 + lane];
          mma16(oacc[mt][nf], oa0, oa1, oa2, oa3, B.x, B.y);
        }
      }
    }
  }

  // ---- epilogue: + bo, store ----
#pragma unroll
  for (int mt = 0; mt < 2; mt++) {
    int row = s * 256 + w * 32 + mt * 16 + r4;
#pragma unroll
    for (int nf = 0; nf < 8; nf++) {
      int col = nf * 8 + 2 * c4;
      float2 bb = *(const float2*)(bo + col);
      *(float2*)(outg + (size_t)row * 64 + col) =
          make_float2(oacc[mt][nf].x + bb.x, oacc[mt][nf].y + bb.y);
      *(float2*)(outg + (size_t)(row + 8) * 64 + col) =
          make_float2(oacc[mt][nf].z + bb.x, oacc[mt][nf].w + bb.y);
    }
  }
}

// ---------------------------------------------------------------------------
extern "C" void kernel_launch(void* const* d_in, const int* in_sizes, int n_in,
                              void* d_out, int out_size) {
  const float* input_q  = (const float*)d_in[0];
  const float* input_kv = (const float*)d_in[1];
  const float* mask     = (const float*)d_in[2];
  const float* bias     = (const float*)d_in[3];
  const float* wq       = (const float*)d_in[4];
  const float* wk       = (const float*)d_in[5];
  const float* wv       = (const float*)d_in[6];
  const float* wo       = (const float*)d_in[7];
  const float* bo       = (const float*)d_in[8];
  float* out = (float*)d_out;

  cudaFuncSetAttribute(fused_kernel, cudaFuncAttributeMaxDynamicSharedMemorySize,
                       FUSED_SMEM);

  prep_kernel<<<128, 256>>>(wq, wk, wv, wo);
  stageb_kernel<<<4096, 256>>>(bias);
  fused_kernel<<<S_LEN, 256, FUSED_SMEM>>>(input_q, input_kv, mask, bo, out);
}

// round 10
// speedup vs baseline: 1.2842x; 1.0663x over previous
#include <cuda_runtime.h>
#include <cuda_fp16.h>

#define S_LEN 128
#define NH 8
#define INF9 1.0e9f

// Weight fragments in fp16 B-frag layout (uint = half2), prepped per launch.
__device__ unsigned g_Wfu[3 * 8 * 1024];   // [z][h][kg4][nf4][lane32][p2]
__device__ unsigned g_Wofu[8 * 1024];      // [h][kg2][nf8][lane32][p2]
__device__ unsigned g_B16[262144];         // bias as half2 pairs (same order)

__device__ __forceinline__ unsigned pk(float a, float b) {
  __half2 h = __floats2half2_rn(a, b);
  return *(unsigned*)&h;
}
__device__ __forceinline__ float2 h22f2(unsigned u) {
  __half2 h = *(__half2*)&u;
  return __half22float2(h);
}

// D += A(16x16 f16) * B(16x8 f16), fp32 accum.
__device__ __forceinline__ void mma16(float4& c, unsigned a0, unsigned a1,
                                      unsigned a2, unsigned a3, unsigned b0,
                                      unsigned b1) {
  asm volatile(
      "mma.sync.aligned.m16n8k16.row.col.f32.f16.f16.f32 "
      "{%0,%1,%2,%3}, {%4,%5,%6,%7}, {%8,%9}, {%0,%1,%2,%3};"
      : "+f"(c.x), "+f"(c.y), "+f"(c.z), "+f"(c.w)
      : "r"(a0), "r"(a1), "r"(a2), "r"(a3), "r"(b0), "r"(b1));
}

// ---------------------------------------------------------------------------
// Prep: weights -> per-head fp16 B-frag layouts (wq pre-scaled), AND
// bias fp32 -> fp16 pairs. One kernel, 294912 work items.
// ---------------------------------------------------------------------------
__global__ void prep_kernel(const float* __restrict__ wq,
                            const float* __restrict__ wk,
                            const float* __restrict__ wv,
                            const float* __restrict__ wo,
                            const float* __restrict__ bias) {
  const float scale = 0.17677669529663687f;  // 1/sqrt(32)
  int id = blockIdx.x * 256 + threadIdx.x;
  if (id < 24576) {
    int p = id & 1, lane = (id >> 1) & 31, nf = (id >> 6) & 3,
        kg = (id >> 8) & 3, h = (id >> 10) & 7, z = id >> 13;
    int r4 = lane >> 2, c4 = lane & 3;
    const float* w = (z == 0) ? wq : (z == 1) ? wk : wv;
    int k0 = kg * 16 + 2 * c4 + 8 * p;
    int col = h * 32 + nf * 8 + r4;
    float v0 = w[k0 * 256 + col], v1 = w[(k0 + 1) * 256 + col];
    if (z == 0) { v0 *= scale; v1 *= scale; }
    g_Wfu[id] = pk(v0, v1);
  } else if (id < 32768) {
    int id2 = id - 24576;
    int p = id2 & 1, lane = (id2 >> 1) & 31, nf = (id2 >> 6) & 7,
        kg = (id2 >> 9) & 1, h = id2 >> 10;
    int r4 = lane >> 2, c4 = lane & 3;
    int k0 = kg * 16 + 2 * c4 + 8 * p;
    int col = nf * 8 + r4;
    g_Wofu[id2] = pk(wo[(h * 32 + k0) * 64 + col],
                     wo[(h * 32 + k0 + 1) * 64 + col]);
  } else {
    int id2 = id - 32768;  // [0, 262144)
    float2 v = ((const float2*)bias)[id2];
    g_B16[id2] = pk(v.x, v.y);
  }
}

// ---------------------------------------------------------------------------
// Mega-fused kernel: one block per s, 256 threads (8 warps), warp owns 32
// rows (q and kv). fp16 operands, fp32 accum. Bias prefetch depth 2,
// next-head W prefetched into regs during attention, lp via ones-mma.
//
// SMEM (uints): Xq[8192] Xk[8192] W[2x4096] Ks[2x4096] Vs[2x4096] ms[256f]
// ---------------------------------------------------------------------------
#define XQ_OFF 0
#define XK_OFF 8192
#define WS_OFF 16384
#define KS_OFF 24576
#define VS_OFF 32768
#define MS_OFF 40960
#define FUSED_SMEM ((40960 + 256) * 4)
#define ONE2 0x3C003C00u

__global__ __launch_bounds__(256, 1) void fused_kernel(
    const float* __restrict__ xq, const float* __restrict__ xkv,
    const float* __restrict__ mask, const float* __restrict__ bo,
    float* __restrict__ outg) {
  extern __shared__ unsigned smu[];
  float* ms = (float*)(smu + MS_OFF);

  const int tid = threadIdx.x;
  const int s = blockIdx.x;

  // ---- stage Xq, Xkv as fp16 A-frags ----
  for (int i = tid; i < 4096; i += 256) {
    int row = i >> 4, k0 = (i & 15) * 4;
    float4 a = *(const float4*)(xq + (size_t)(s * 256 + row) * 64 + k0);
    float4 b = *(const float4*)(xkv + (size_t)(s * 256 + row) * 64 + k0);
    int rt = row >> 4, kg = k0 >> 4;
    int r4s = row & 7, eR = (row >> 3) & 1;
    int pi0 = (k0 & 15) >> 1;
    int c4a = pi0 & 3, hi = pi0 >> 2;
    int reg = eR + 2 * hi;
    int base = (((rt * 4 + kg) * 32 + r4s * 4 + c4a) * 4) + reg;
    smu[XQ_OFF + base] = pk(a.x, a.y);
    smu[XQ_OFF + base + 4] = pk(a.z, a.w);
    smu[XK_OFF + base] = pk(b.x, b.y);
    smu[XK_OFF + base + 4] = pk(b.z, b.w);
  }
  ms[tid] = (mask[s * 256 + tid] - 1.0f) * INF9 - 4.0f;  // -4: exp headroom

  const int w = tid >> 5, lane = tid & 31;
  const int r4 = lane >> 2, c4 = lane & 3;
  const int rt0 = w * 2;

  const uint4* Xq4 = (const uint4*)(smu + XQ_OFF);
  const uint4* Xk4 = (const uint4*)(smu + XK_OFF);

  // pre-stage W for head 0 into parity buffer 0
  {
    uint4* dst = (uint4*)(smu + WS_OFF);
#pragma unroll
    for (int j = 0; j < 4; j++) {
      dst[j * 256 + tid] = (j < 3) ? ((const uint4*)g_Wfu)[(j * 8) * 256 + tid]
                                   : ((const uint4*)g_Wofu)[tid];
    }
  }

  float4 oacc[2][8];
#pragma unroll
  for (int i = 0; i < 2; i++)
#pragma unroll
    for (int j = 0; j < 8; j++) oacc[i][j] = make_float4(0.f, 0.f, 0.f, 0.f);

#pragma unroll 1
  for (int h = 0; h < NH; h++) {
    const int p = h & 1;
    const uint2* Ws2 = (const uint2*)(smu + WS_OFF + p * 4096);
    const uint2* Ks2 = (const uint2*)(smu + KS_OFF + p * 4096);
    const uint2* Vs2 = (const uint2*)(smu + VS_OFF + p * 4096);

    __syncthreads();  // W[p] visible; Ks/Vs[p] safe to overwrite

    // ---- Q = Xq @ Wq_h -> qa A-frags ----
    uint4 qa[2][2];
    {
      float4 acc[2][4];
#pragma unroll
      for (int i = 0; i < 2; i++)
#pragma unroll
        for (int j = 0; j < 4; j++) acc[i][j] = make_float4(0.f, 0.f, 0.f, 0.f);
#pragma unroll
      for (int kg = 0; kg < 4; kg++) {
        uint4 A0 = Xq4[(rt0 * 4 + kg) * 32 + lane];
        uint4 A1 = Xq4[((rt0 + 1) * 4 + kg) * 32 + lane];
#pragma unroll
        for (int nf = 0; nf < 4; nf++) {
          uint2 B = Ws2[(kg * 4 + nf) * 32 + lane];
          mma16(acc[0][nf], A0.x, A0.y, A0.z, A0.w, B.x, B.y);
          mma16(acc[1][nf], A1.x, A1.y, A1.z, A1.w, B.x, B.y);
        }
      }
#pragma unroll
      for (int mt = 0; mt < 2; mt++)
#pragma unroll
        for (int kg = 0; kg < 2; kg++)
          qa[mt][kg] = make_uint4(pk(acc[mt][2 * kg].x, acc[mt][2 * kg].y),
                                  pk(acc[mt][2 * kg].z, acc[mt][2 * kg].w),
                                  pk(acc[mt][2 * kg + 1].x, acc[mt][2 * kg + 1].y),
                                  pk(acc[mt][2 * kg + 1].z, acc[mt][2 * kg + 1].w));
    }

    // ---- K = Xkv @ Wk_h -> Ks[p] scatter ----
    {
      float4 acc[2][4];
#pragma unroll
      for (int i = 0; i < 2; i++)
#pragma unroll
        for (int j = 0; j < 4; j++) acc[i][j] = make_float4(0.f, 0.f, 0.f, 0.f);
#pragma unroll
      for (int kg = 0; kg < 4; kg++) {
        uint4 A0 = Xk4[(rt0 * 4 + kg) * 32 + lane];
        uint4 A1 = Xk4[((rt0 + 1) * 4 + kg) * 32 + lane];
#pragma unroll
        for (int nf = 0; nf < 4; nf++) {
          uint2 B = Ws2[512 + (kg * 4 + nf) * 32 + lane];
          mma16(acc[0][nf], A0.x, A0.y, A0.z, A0.w, B.x, B.y);
          mma16(acc[1][nf], A1.x, A1.y, A1.z, A1.w, B.x, B.y);
        }
      }
#pragma unroll
      for (int mt = 0; mt < 2; mt++) {
        int kt = w * 2 + mt;
#pragma unroll
        for (int nf = 0; nf < 4; nf++) {
          int kgd = nf >> 1, pp = nf & 1;
          smu[KS_OFF + p * 4096 + (((kt * 2 + kgd) * 2 + 0) * 32 + lane) * 2 + pp] =
              pk(acc[mt][nf].x, acc[mt][nf].y);
          smu[KS_OFF + p * 4096 + (((kt * 2 + kgd) * 2 + 1) * 32 + lane) * 2 + pp] =
              pk(acc[mt][nf].z, acc[mt][nf].w);
        }
      }
    }

    // ---- V = Xkv @ Wv_h -> Vs[p] scatter ----
    {
      float4 acc[2][4];
#pragma unroll
      for (int i = 0; i < 2; i++)
#pragma unroll
        for (int j = 0; j < 4; j++) acc[i][j] = make_float4(0.f, 0.f, 0.f, 0.f);
#pragma unroll
      for (int kg = 0; kg < 4; kg++) {
        uint4 A0 = Xk4[(rt0 * 4 + kg) * 32 + lane];
        uint4 A1 = Xk4[((rt0 + 1) * 4 + kg) * 32 + lane];
#pragma unroll
        for (int nf = 0; nf < 4; nf++) {
          uint2 B = Ws2[1024 + (kg * 4 + nf) * 32 + lane];
          mma16(acc[0][nf], A0.x, A0.y, A0.z, A0.w, B.x, B.y);
          mma16(acc[1][nf], A1.x, A1.y, A1.z, A1.w, B.x, B.y);
        }
      }
      __half* Vh = (__half*)(smu + VS_OFF + p * 4096);
      int e = r4 & 1, cp = r4 >> 1;
#pragma unroll
      for (int mt = 0; mt < 2; mt++) {
        int kt = w * 2 + mt;
#pragma unroll
        for (int nf = 0; nf < 4; nf++) {
          int b0 = (((kt * 4 + nf) * 32 + (2 * c4) * 4 + cp) * 4) + e;
          int b1 = b0 + 16;
          Vh[b0] = __float2half_rn(acc[mt][nf].x);
          Vh[b0 + 2] = __float2half_rn(acc[mt][nf].z);
          Vh[b1] = __float2half_rn(acc[mt][nf].y);
          Vh[b1 + 2] = __float2half_rn(acc[mt][nf].w);
        }
      }
    }
    __syncthreads();  // Ks/Vs[p] ready

    // ---- prefetch next head's W into regs (overlaps with attention) ----
    uint4 wreg[4];
    if (h < NH - 1) {
#pragma unroll
      for (int j = 0; j < 4; j++)
        wreg[j] = (j < 3)
                      ? ((const uint4*)g_Wfu)[(j * 8 + h + 1) * 256 + tid]
                      : ((const uint4*)g_Wofu)[(h + 1) * 256 + tid];
    }

    // ---- attention ----
    float4 o[2][4];
#pragma unroll
    for (int mt = 0; mt < 2; mt++)
#pragma unroll
      for (int nf = 0; nf < 4; nf++) o[mt][nf] = make_float4(0.f, 0.f, 0.f, 0.f);
    float4 lpq[2] = {make_float4(0.f, 0.f, 0.f, 0.f),
                     make_float4(0.f, 0.f, 0.f, 0.f)};

    const unsigned* bb0[2]; const unsigned* bb1[2];
#pragma unroll
    for (int mt = 0; mt < 2; mt++) {
      bb0[mt] = g_B16 + h * 32768 + (w * 32 + mt * 16 + r4) * 128 + c4;
      bb1[mt] = bb0[mt] + 8 * 128;
    }
    // bias slots for kt and kt+1 (prefetch distance 2)
    unsigned cbuf[2][2][2][2];  // [slot][mt][nt][rowpair]
#pragma unroll
    for (int sl = 0; sl < 2; sl++)
#pragma unroll
      for (int mt = 0; mt < 2; mt++)
#pragma unroll
        for (int nt = 0; nt < 2; nt++) {
          cbuf[sl][mt][nt][0] = bb0[mt][sl * 8 + nt * 4];
          cbuf[sl][mt][nt][1] = bb1[mt][sl * 8 + nt * 4];
        }

#pragma unroll 2
    for (int kt = 0; kt < 16; kt++) {
      const int kv0 = kt * 16;
      const int sl = kt & 1;

      float2 m0 = *(const float2*)(ms + kv0 + 2 * c4);
      float2 m1 = *(const float2*)(ms + kv0 + 8 + 2 * c4);

      float4 Sf[2][2];
#pragma unroll
      for (int mt = 0; mt < 2; mt++) {
        float2 c00 = h22f2(cbuf[sl][mt][0][0]), c01 = h22f2(cbuf[sl][mt][0][1]);
        float2 c10 = h22f2(cbuf[sl][mt][1][0]), c11 = h22f2(cbuf[sl][mt][1][1]);
        Sf[mt][0] = make_float4(c00.x + m0.x, c00.y + m0.y,
                                c01.x + m0.x, c01.y + m0.y);
        Sf[mt][1] = make_float4(c10.x + m1.x, c10.y + m1.y,
                                c11.x + m1.x, c11.y + m1.y);
      }

      // prefetch bias for kt+2 into the slot just consumed
      if (kt < 14) {
#pragma unroll
        for (int mt = 0; mt < 2; mt++)
#pragma unroll
          for (int nt = 0; nt < 2; nt++) {
            cbuf[sl][mt][nt][0] = bb0[mt][(kt + 2) * 8 + nt * 4];
            cbuf[sl][mt][nt][1] = bb1[mt][(kt + 2) * 8 + nt * 4];
          }
      }

#pragma unroll
      for (int kg = 0; kg < 2; kg++) {
        uint2 Kb0 = Ks2[((kt * 2 + kg) * 2 + 0) * 32 + lane];
        uint2 Kb1 = Ks2[((kt * 2 + kg) * 2 + 1) * 32 + lane];
#pragma unroll
        for (int mt = 0; mt < 2; mt++) {
          mma16(Sf[mt][0], qa[mt][kg].x, qa[mt][kg].y, qa[mt][kg].z,
                qa[mt][kg].w, Kb0.x, Kb0.y);
          mma16(Sf[mt][1], qa[mt][kg].x, qa[mt][kg].y, qa[mt][kg].z,
                qa[mt][kg].w, Kb1.x, Kb1.y);
        }
      }

      uint2 Vb[4];
#pragma unroll
      for (int nf = 0; nf < 4; nf++) Vb[nf] = Vs2[(kt * 4 + nf) * 32 + lane];

#pragma unroll
      for (int mt = 0; mt < 2; mt++) {
        float p00 = __expf(Sf[mt][0].x), p01 = __expf(Sf[mt][0].y);
        float p02 = __expf(Sf[mt][0].z), p03 = __expf(Sf[mt][0].w);
        float p10 = __expf(Sf[mt][1].x), p11 = __expf(Sf[mt][1].y);
        float p12 = __expf(Sf[mt][1].z), p13 = __expf(Sf[mt][1].w);
        unsigned pa0 = pk(p00, p01), pa1 = pk(p02, p03);
        unsigned pa2 = pk(p10, p11), pa3 = pk(p12, p13);
        // lp via ones-mma: exact fp32 row-sums of the SAME fp16 P
        mma16(lpq[mt], pa0, pa1, pa2, pa3, ONE2, ONE2);
#pragma unroll
        for (int nf = 0; nf < 4; nf++)
          mma16(o[mt][nf], pa0, pa1, pa2, pa3, Vb[nf].x, Vb[nf].y);
      }
    }

    // ---- normalize O, pack to A-frags, oacc += O @ Wo_h ----
#pragma unroll
    for (int mt = 0; mt < 2; mt++) {
      float inv0 = 1.0f / lpq[mt].x;   // row r4 sum
      float inv8 = 1.0f / lpq[mt].z;   // row r4+8 sum
#pragma unroll
      for (int kg = 0; kg < 2; kg++) {
        unsigned oa0 = pk(o[mt][2 * kg].x * inv0, o[mt][2 * kg].y * inv0);
        unsigned oa1 = pk(o[mt][2 * kg].z * inv8, o[mt][2 * kg].w * inv8);
        unsigned oa2 = pk(o[mt][2 * kg + 1].x * inv0, o[mt][2 * kg + 1].y * inv0);
        unsigned oa3 = pk(o[mt][2 * kg + 1].z * inv8, o[mt][2 * kg + 1].w * inv8);
#pragma unroll
        for (int nf = 0; nf < 8; nf++) {
          uint2 B = Ws2[1536 + (kg * 8 + nf) * 32 + lane];
          mma16(oacc[mt][nf], oa0, oa1, oa2, oa3, B.x, B.y);
        }
      }
    }

    // ---- store prefetched next-head W into opposite parity buffer ----
    if (h < NH - 1) {
      uint4* dst = (uint4*)(smu + WS_OFF + (p ^ 1) * 4096);
#pragma unroll
      for (int j = 0; j < 4; j++) dst[j * 256 + tid] = wreg[j];
    }
  }

  // ---- epilogue: + bo, store ----
#pragma unroll
  for (int mt = 0; mt < 2; mt++) {
    int row = s * 256 + w * 32 + mt * 16 + r4;
#pragma unroll
    for (int nf = 0; nf < 8; nf++) {
      int col = nf * 8 + 2 * c4;
      float2 bb = *(const float2*)(bo + col);
      *(float2*)(outg + (size_t)row * 64 + col) =
          make_float2(oacc[mt][nf].x + bb.x, oacc[mt][nf].y + bb.y);
      *(float2*)(outg + (size_t)(row + 8) * 64 + col) =
          make_float2(oacc[mt][nf].z + bb.x, oacc[mt][nf].w + bb.y);
    }
  }
}

// ---------------------------------------------------------------------------
extern "C" void kernel_launch(void* const* d_in, const int* in_sizes, int n_in,
                              void* d_out, int out_size) {
  const float* input_q  = (const float*)d_in[0];
  const float* input_kv = (const float*)d_in[1];
  const float* mask     = (const float*)d_in[2];
  const float* bias     = (const float*)d_in[3];
  const float* wq       = (const float*)d_in[4];
  const float* wk       = (const float*)d_in[5];
  const float* wv       = (const float*)d_in[6];
  const float* wo       = (const float*)d_in[7];
  const float* bo       = (const float*)d_in[8];
  float* out = (float*)d_out;

  cudaFuncSetAttribute(fused_kernel, cudaFuncAttributeMaxDynamicSharedMemorySize,
                       FUSED_SMEM);

  prep_kernel<<<1152, 256>>>(wq, wk, wv, wo, bias);
  fused_kernel<<<S_LEN, 256, FUSED_SMEM>>>(input_q, input_kv, mask, bo, out);
}